// round 1
// baseline (speedup 1.0000x reference)
#include <cuda_runtime.h>
#include <cstdint>

// Problem constants
#define IMG_W   1024
#define IMG_H   1024
#define N_IMG   32
#define IMG_PIX (IMG_W * IMG_H)            // 1,048,576
#define TOTAL_PIX ((size_t)N_IMG * IMG_PIX) // 33,554,432
#define N_ITER  25
#define SMOOTH  1e-5

// Tile config: one skeleton iteration fused per launch.
// erode(img) -> img'; erode(img') -> e2; dilate(e2) -> open; pointwise skel update.
// Needs halo 3 on the input image tile.
#define TB    64                 // output tile side
#define HALO  3
#define RR    (TB + 2 * HALO)    // 70 : loaded region side
#define STR   (RR + 1)           // 71 : smem row stride (odd -> conflict-free columns)
#define NTHR  256

// Scratch (device globals: no cudaMalloc allowed)
__device__ float g_bufA[TOTAL_PIX];
__device__ float g_bufB[TOTAL_PIX];
__device__ float g_skel[TOTAL_PIX];
__device__ double g_sums[4];

__device__ __forceinline__ float finf()  { return __int_as_float(0x7f800000); }
__device__ __forceinline__ float fninf() { return __int_as_float(0xff800000); }

// One fused skeleton iteration.
// FIRST = true : e1 = img (no erode), skel = relu(e1 - dilate(erode(e1))), img not written.
// FIRST = false: e1 = erode(img) written to img_out; delta = relu(e1 - dilate(erode(e1)));
//                skel += relu(delta - skel*delta).
template <bool FIRST>
__global__ __launch_bounds__(NTHR) void skel_iter(const float* __restrict__ img_in,
                                                  float* __restrict__ img_out,
                                                  float* __restrict__ skel) {
    __shared__ float sA[RR * STR];
    __shared__ float sB[RR * STR];

    const int tx = blockIdx.x;
    const int ty = blockIdx.y;
    const int n  = blockIdx.z;
    const int x0 = tx * TB - HALO;
    const int y0 = ty * TB - HALO;
    const int tid = threadIdx.x;

    const float* in = img_in + (size_t)n * IMG_PIX;
    const float INF = finf();
    const float NINF = fninf();

    // Load img tile (halo 3); out-of-image -> +inf (excluded from mins)
    for (int i = tid; i < RR * RR; i += NTHR) {
        const int ly = i / RR, lx = i - ly * RR;
        const int gy = y0 + ly, gx = x0 + lx;
        float v = INF;
        if (gy >= 0 && gy < IMG_H && gx >= 0 && gx < IMG_W)
            v = in[gy * IMG_W + gx];
        sA[ly * STR + lx] = v;
    }
    __syncthreads();

    // e1 = erode(img) (or copy if FIRST) on region with halo 2.
    // Out-of-image positions forced to +inf (next erode must exclude them).
    {
        const int R1 = RR - 2; // 68
        for (int i = tid; i < R1 * R1; i += NTHR) {
            const int ly = i / R1 + 1, lx = i % R1 + 1;
            const int gy = y0 + ly, gx = x0 + lx;
            float v;
            if (gy < 0 || gy >= IMG_H || gx < 0 || gx >= IMG_W) {
                v = INF;
            } else if (FIRST) {
                v = sA[ly * STR + lx];
            } else {
                const float c = sA[ly * STR + lx];
                const float u = sA[(ly - 1) * STR + lx];
                const float d = sA[(ly + 1) * STR + lx];
                const float l = sA[ly * STR + lx - 1];
                const float r = sA[ly * STR + lx + 1];
                v = fminf(fminf(fminf(u, d), fminf(l, r)), c);
            }
            sB[ly * STR + lx] = v;
        }
    }
    __syncthreads();

    // e2 = erode(e1) on region with halo 1, into sA.
    // Out-of-image positions forced to -inf (dilate must exclude them).
    {
        const int R2 = RR - 4; // 66
        for (int i = tid; i < R2 * R2; i += NTHR) {
            const int ly = i / R2 + 2, lx = i % R2 + 2;
            const int gy = y0 + ly, gx = x0 + lx;
            float v;
            if (gy < 0 || gy >= IMG_H || gx < 0 || gx >= IMG_W) {
                v = NINF;
            } else {
                const float c = sB[ly * STR + lx];
                const float u = sB[(ly - 1) * STR + lx];
                const float d = sB[(ly + 1) * STR + lx];
                const float l = sB[ly * STR + lx - 1];
                const float r = sB[ly * STR + lx + 1];
                v = fminf(fminf(fminf(u, d), fminf(l, r)), c);
            }
            sA[ly * STR + lx] = v;
        }
    }
    __syncthreads();

    // open = dilate(e2); delta = relu(e1 - open); skel update; write img'
    for (int i = tid; i < TB * TB; i += NTHR) {
        const int ly = i / TB + HALO, lx = i % TB + HALO;
        const int gy = y0 + ly, gx = x0 + lx; // always in-image (1024 % 64 == 0)

        float o = NINF;
#pragma unroll
        for (int dy = -1; dy <= 1; dy++) {
#pragma unroll
            for (int dx = -1; dx <= 1; dx++) {
                o = fmaxf(o, sA[(ly + dy) * STR + (lx + dx)]);
            }
        }
        const float e1 = sB[ly * STR + lx];
        const float delta = fmaxf(e1 - o, 0.0f);

        const size_t g = (size_t)n * IMG_PIX + (size_t)gy * IMG_W + gx;
        if (!FIRST) img_out[g] = e1;

        float s;
        if (FIRST) {
            s = delta;
        } else {
            const float so = skel[g];
            s = so + fmaxf(delta - so * delta, 0.0f);
        }
        skel[g] = s;
    }
}

__global__ void zero_sums(double* sums) {
    if (threadIdx.x < 4) sums[threadIdx.x] = 0.0;
}

// sums[base]   += sum(skel * other)
// sums[base+1] += sum(skel)
__global__ __launch_bounds__(256) void reduce_skel(const float* __restrict__ skel,
                                                   const float* __restrict__ other,
                                                   double* __restrict__ sums, int base) {
    const size_t n4 = TOTAL_PIX / 4;
    const float4* s4 = (const float4*)skel;
    const float4* o4 = (const float4*)other;

    float acc_p = 0.0f, acc_s = 0.0f;
    const size_t stride = (size_t)gridDim.x * blockDim.x;
    for (size_t i = (size_t)blockIdx.x * blockDim.x + threadIdx.x; i < n4; i += stride) {
        const float4 a = s4[i];
        const float4 b = o4[i];
        acc_p += a.x * b.x + a.y * b.y + a.z * b.z + a.w * b.w;
        acc_s += a.x + a.y + a.z + a.w;
    }
    // warp reduce
#pragma unroll
    for (int off = 16; off > 0; off >>= 1) {
        acc_p += __shfl_down_sync(0xffffffffu, acc_p, off);
        acc_s += __shfl_down_sync(0xffffffffu, acc_s, off);
    }
    if ((threadIdx.x & 31) == 0) {
        atomicAdd(&sums[base], (double)acc_p);
        atomicAdd(&sums[base + 1], (double)acc_s);
    }
}

__global__ void finalize_cldice(const double* __restrict__ sums, float* __restrict__ out) {
    // sums[0] = sum(skel_pred * target), sums[1] = sum(skel_pred)
    // sums[2] = sum(skel_true * inputs), sums[3] = sum(skel_true)
    const double tprec = (sums[0] + SMOOTH) / (sums[1] + SMOOTH);
    const double tsens = (sums[2] + SMOOTH) / (sums[3] + SMOOTH);
    out[0] = (float)(1.0 - 2.0 * (tprec * tsens) / (tprec + tsens));
}

extern "C" void kernel_launch(void* const* d_in, const int* in_sizes, int n_in,
                              void* d_out, int out_size) {
    const float* target = (const float*)d_in[0];
    const float* inputs = (const float*)d_in[1];
    float* out = (float*)d_out;

    static float* bufA = nullptr;
    static float* bufB = nullptr;
    static float* skel = nullptr;
    static double* sums = nullptr;
    if (!bufA) {
        cudaGetSymbolAddress((void**)&bufA, g_bufA);
        cudaGetSymbolAddress((void**)&bufB, g_bufB);
        cudaGetSymbolAddress((void**)&skel, g_skel);
        cudaGetSymbolAddress((void**)&sums, g_sums);
    }

    const dim3 grid(IMG_W / TB, IMG_H / TB, N_IMG);
    const dim3 block(NTHR);

    zero_sums<<<1, 32>>>(sums);

    for (int t = 0; t < 2; t++) {
        // t=0: skel_pred = soft_skel(inputs), cross-term with target
        // t=1: skel_true = soft_skel(target), cross-term with inputs
        const float* x     = (t == 0) ? inputs : target;
        const float* other = (t == 0) ? target : inputs;

        // init: skel = relu(x - open(x)), img stays x
        skel_iter<true><<<grid, block>>>(x, nullptr, skel);

        const float* cur = x;
        float* nxt = bufA;
        for (int j = 0; j < N_ITER; j++) {
            skel_iter<false><<<grid, block>>>(cur, nxt, skel);
            cur = nxt;
            nxt = (nxt == bufA) ? bufB : bufA;
        }

        reduce_skel<<<2048, 256>>>(skel, other, sums, t * 2);
    }

    finalize_cldice<<<1, 1>>>(sums, out);
}

// round 2
// speedup vs baseline: 2.3152x; 2.3152x over previous
#include <cuda_runtime.h>
#include <cstdint>

#define IMG_W   1024
#define IMG_H   1024
#define N_IMG   32
#define IMG_PIX (IMG_W * IMG_H)
#define TOTAL_PIX ((size_t)N_IMG * IMG_PIX)
#define SMOOTH  1e-5
#define BAND    256
#define NBANDS  (IMG_H / BAND)
#define GROUPS  256              // 256 float4 groups per 1024-wide row
#define SKELD   12               // skel ring depth (span needed: T+1 <= 10)

// Scratch (no cudaMalloc allowed)
__device__ float g_bufA[TOTAL_PIX];
__device__ float g_bufB[TOTAL_PIX];
__device__ float g_skel[TOTAL_PIX];
__device__ double g_sums[4];

__device__ __forceinline__ float4 ld4(const float* p) { return *(const float4*)p; }
__device__ __forceinline__ void st4(float* p, float4 v) { *(float4*)p = v; }
__device__ __forceinline__ float mn3(float a, float b, float c) { return fminf(a, fminf(b, c)); }
__device__ __forceinline__ float mx3(float a, float b, float c) { return fmaxf(a, fmaxf(b, c)); }

__device__ __forceinline__ void skel_upd(float4& s, const float4& d) {
    s.x += fmaxf(fmaf(-s.x, d.x, d.x), 0.0f);
    s.y += fmaxf(fmaf(-s.y, d.y, d.y), 0.0f);
    s.z += fmaxf(fmaf(-s.z, d.z, d.z), 0.0f);
    s.w += fmaxf(fmaf(-s.w, d.w, d.w), 0.0f);
}

// Erosion-tower pass: from input I = E_base, computes levels L_1..L_T (L_j = erode^j(I)),
// deltas for j = 0..T-1: delta_j = relu(L_j - dilate(L_{j+1})), applies the skel
// recurrence, optionally writes L_T to geout for the next pass.
// Each block: full 1024-wide band, sweeps rows. Levels live in smem as 4-row rings.
template <int T, bool INIT, bool WRITE_E>
__global__ __launch_bounds__(GROUPS)
void tower_pass(const float* __restrict__ gin,
                float* __restrict__ geout,
                float* __restrict__ gskel)
{
    extern __shared__ float sm[];   // (T+1) level rings of 4 rows + skel ring of SKELD rows
    const int t  = threadIdx.x;     // float4 group id, x = 4t
    const int y0 = blockIdx.x * BAND;
    const int y1 = y0 + BAND;
    const int n  = blockIdx.y;
    const float INF  = __int_as_float(0x7f800000);
    const float NINF = -INF;

    const float4* in4   = (const float4*)(gin + (size_t)n * IMG_PIX);
    float4*       eout4 = (float4*)(WRITE_E ? (geout + (size_t)n * IMG_PIX) : nullptr);
    float4*       skel4 = (float4*)(gskel + (size_t)n * IMG_PIX);

    float* const skelring = sm + (T + 1) * 4 * IMG_W;
    const int x4 = 4 * t;

    // Prefill level rings with +inf (correct padding for rows above image / pre-sweep)
    {
        const float4 inf4 = make_float4(INF, INF, INF, INF);
        float4* s4 = (float4*)sm;
        const int tot = (T + 1) * 4 * GROUPS;
        for (int i = t; i < tot; i += GROUPS) s4[i] = inf4;
    }
    __syncthreads();

    for (int Y = y0 - T - 1; Y <= y1 + T; ++Y) {
        // Phase 0: load input row Y into level-0 ring (+inf outside image)
        {
            float4 v = make_float4(INF, INF, INF, INF);
            if (Y >= 0 && Y < IMG_H) v = in4[Y * GROUPS + t];
            st4(sm + (Y & 3) * IMG_W + x4, v);
        }
        __syncthreads();

        // Phase 1: erosion levels, L_j row (Y - j)
#pragma unroll
        for (int j = 1; j <= T; ++j) {
            const int r = Y - j;
            const float* L  = sm + (j - 1) * 4 * IMG_W;
            const float* ru = L + ((r - 1) & 3) * IMG_W;
            const float* rc = L + (r & 3) * IMG_W;
            const float* rd = L + ((r + 1) & 3) * IMG_W;
            const float4 u = ld4(ru + x4);
            const float4 c = ld4(rc + x4);
            const float4 d = ld4(rd + x4);
            const float cl = (t == 0)          ? INF : rc[x4 - 1];
            const float cr = (t == GROUPS - 1) ? INF : rc[x4 + 4];
            float4 o;
            o.x = fminf(mn3(u.x, c.x, d.x), fminf(cl,  c.y));
            o.y = fminf(mn3(u.y, c.y, d.y), fminf(c.x, c.z));
            o.z = fminf(mn3(u.z, c.z, d.z), fminf(c.y, c.w));
            o.w = fminf(mn3(u.w, c.w, d.w), fminf(c.z, cr));
            st4(sm + j * 4 * IMG_W + (r & 3) * IMG_W + x4, o);
            if (WRITE_E && j == T) {
                if (r >= y0 && r < y1) eout4[r * GROUPS + t] = o;
            }
            __syncthreads();
        }

        // Phase 2: deltas + skel recurrence (reads rings only; skel rows are
        // per-thread-owned -> no barrier needed)
#pragma unroll
        for (int j = 0; j < T; ++j) {
            const int y = Y - j - 2;
            if (y < y0 || y >= y1) continue;

            const float* Lb = sm + (j + 1) * 4 * IMG_W;   // dilate input = L_{j+1}
            const float* ra = Lb + ((y - 1) & 3) * IMG_W;
            const float* rb = Lb + (y & 3) * IMG_W;
            const float* rc = Lb + ((y + 1) & 3) * IMG_W;
            float4 a = ld4(ra + x4);
            float4 b = ld4(rb + x4);
            float4 c = ld4(rc + x4);
            float al = (t == 0) ? NINF : ra[x4 - 1];
            float bl = (t == 0) ? NINF : rb[x4 - 1];
            float cl = (t == 0) ? NINF : rc[x4 - 1];
            float ar = (t == GROUPS - 1) ? NINF : ra[x4 + 4];
            float br = (t == GROUPS - 1) ? NINF : rb[x4 + 4];
            float cr = (t == GROUPS - 1) ? NINF : rc[x4 + 4];
            if (y == 0)         { a = make_float4(NINF, NINF, NINF, NINF); al = NINF; ar = NINF; }
            if (y == IMG_H - 1) { c = make_float4(NINF, NINF, NINF, NINF); cl = NINF; cr = NINF; }

            float4 vm;
            vm.x = mx3(a.x, b.x, c.x);
            vm.y = mx3(a.y, b.y, c.y);
            vm.z = mx3(a.z, b.z, c.z);
            vm.w = mx3(a.w, b.w, c.w);
            const float vl = mx3(al, bl, cl);
            const float vr = mx3(ar, br, cr);
            float4 op;
            op.x = fmaxf(vm.x, fmaxf(vl,   vm.y));
            op.y = fmaxf(vm.y, fmaxf(vm.x, vm.z));
            op.z = fmaxf(vm.z, fmaxf(vm.y, vm.w));
            op.w = fmaxf(vm.w, fmaxf(vm.z, vr));

            const float* La = sm + j * 4 * IMG_W;         // E-level for this delta
            const float4 e = ld4(La + (y & 3) * IMG_W + x4);
            float4 dl;
            dl.x = fmaxf(e.x - op.x, 0.0f);
            dl.y = fmaxf(e.y - op.y, 0.0f);
            dl.z = fmaxf(e.z - op.z, 0.0f);
            dl.w = fmaxf(e.w - op.w, 0.0f);

            float* srow = skelring + (y % SKELD) * IMG_W + x4;
            float4 s;
            if (j == 0) {
                if (INIT) {
                    s = dl;                                // skel = relu(delta_0), delta_0 >= 0
                } else {
                    s = skel4[y * GROUPS + t];
                    skel_upd(s, dl);
                }
            } else {
                s = ld4(srow);
                skel_upd(s, dl);
            }
            if (j == T - 1) skel4[y * GROUPS + t] = s;
            else            st4(srow, s);
        }
    }
}

__global__ void zero_sums(double* sums) {
    if (threadIdx.x < 4) sums[threadIdx.x] = 0.0;
}

__global__ __launch_bounds__(256) void reduce_skel(const float* __restrict__ skel,
                                                   const float* __restrict__ other,
                                                   double* __restrict__ sums, int base) {
    const size_t n4 = TOTAL_PIX / 4;
    const float4* s4 = (const float4*)skel;
    const float4* o4 = (const float4*)other;

    float acc_p = 0.0f, acc_s = 0.0f;
    const size_t stride = (size_t)gridDim.x * blockDim.x;
    for (size_t i = (size_t)blockIdx.x * blockDim.x + threadIdx.x; i < n4; i += stride) {
        const float4 a = s4[i];
        const float4 b = o4[i];
        acc_p += a.x * b.x + a.y * b.y + a.z * b.z + a.w * b.w;
        acc_s += a.x + a.y + a.z + a.w;
    }
#pragma unroll
    for (int off = 16; off > 0; off >>= 1) {
        acc_p += __shfl_down_sync(0xffffffffu, acc_p, off);
        acc_s += __shfl_down_sync(0xffffffffu, acc_s, off);
    }
    if ((threadIdx.x & 31) == 0) {
        atomicAdd(&sums[base],     (double)acc_p);
        atomicAdd(&sums[base + 1], (double)acc_s);
    }
}

__global__ void finalize_cldice(const double* __restrict__ sums, float* __restrict__ out) {
    const double tprec = (sums[0] + SMOOTH) / (sums[1] + SMOOTH);
    const double tsens = (sums[2] + SMOOTH) / (sums[3] + SMOOTH);
    out[0] = (float)(1.0 - 2.0 * (tprec * tsens) / (tprec + tsens));
}

extern "C" void kernel_launch(void* const* d_in, const int* in_sizes, int n_in,
                              void* d_out, int out_size) {
    const float* target = (const float*)d_in[0];
    const float* inputs = (const float*)d_in[1];
    float* out = (float*)d_out;

    static float* bufA = nullptr;
    static float* bufB = nullptr;
    static float* skel = nullptr;
    static double* sums = nullptr;
    static bool attr_done = false;
    if (!bufA) {
        cudaGetSymbolAddress((void**)&bufA, g_bufA);
        cudaGetSymbolAddress((void**)&bufB, g_bufB);
        cudaGetSymbolAddress((void**)&skel, g_skel);
        cudaGetSymbolAddress((void**)&sums, g_sums);
    }
    const int SM9 = (10 * 4 + SKELD) * IMG_W * 4;  // 212992 B
    const int SM8 = (9 * 4 + SKELD) * IMG_W * 4;   // 196608 B
    if (!attr_done) {
        cudaFuncSetAttribute(tower_pass<9, true,  true >, cudaFuncAttributeMaxDynamicSharedMemorySize, SM9);
        cudaFuncSetAttribute(tower_pass<9, false, true >, cudaFuncAttributeMaxDynamicSharedMemorySize, SM9);
        cudaFuncSetAttribute(tower_pass<8, false, false>, cudaFuncAttributeMaxDynamicSharedMemorySize, SM8);
        attr_done = true;
    }

    const dim3 grid(NBANDS, N_IMG);
    const dim3 block(GROUPS);

    zero_sums<<<1, 32>>>(sums);

    for (int tt = 0; tt < 2; tt++) {
        const float* x     = (tt == 0) ? inputs : target;
        const float* other = (tt == 0) ? target : inputs;

        // tower: E_0..E_26, deltas 0..25 (9 + 9 + 8)
        tower_pass<9, true,  true ><<<grid, block, SM9>>>(x,    bufA,    skel);
        tower_pass<9, false, true ><<<grid, block, SM9>>>(bufA, bufB,    skel);
        tower_pass<8, false, false><<<grid, block, SM8>>>(bufB, nullptr, skel);

        reduce_skel<<<2048, 256>>>(skel, other, sums, tt * 2);
    }

    finalize_cldice<<<1, 1>>>(sums, out);
}

// round 3
// speedup vs baseline: 2.6440x; 1.1420x over previous
#include <cuda_runtime.h>
#include <cstdint>

#define IMG_W   1024
#define IMG_H   1024
#define N_IMG   32
#define IMG_PIX (IMG_W * IMG_H)
#define TOTAL_PIX ((size_t)N_IMG * IMG_PIX)
#define SMOOTH  1e-5
#define BAND    256
#define NBANDS  (IMG_H / BAND)
#define GROUPS  256              // 256 float4 groups per 1024-wide row
#define NTHR    512              // 2 rows x 256 groups
#define SKELD   12               // skel ring depth (need T+2 <= 11)

// Scratch (no cudaMalloc allowed)
__device__ float g_bufA[TOTAL_PIX];
__device__ float g_bufB[TOTAL_PIX];
__device__ float g_skel[TOTAL_PIX];
__device__ double g_sums[4];

__device__ __forceinline__ float4 ld4(const float* p) { return *(const float4*)p; }
__device__ __forceinline__ void st4(float* p, float4 v) { *(float4*)p = v; }
__device__ __forceinline__ float mn3(float a, float b, float c) { return fminf(a, fminf(b, c)); }
__device__ __forceinline__ float mx3(float a, float b, float c) { return fmaxf(a, fmaxf(b, c)); }

__device__ __forceinline__ void skel_upd(float4& s, const float4& d) {
    s.x += fmaxf(fmaf(-s.x, d.x, d.x), 0.0f);
    s.y += fmaxf(fmaf(-s.y, d.y, d.y), 0.0f);
    s.z += fmaxf(fmaf(-s.z, d.z, d.z), 0.0f);
    s.w += fmaxf(fmaf(-s.w, d.w, d.w), 0.0f);
}

// delta_j at row y, group g:  relu(E_j[y] - dilate3x3(E_{j+1})[y])
// Level rings: sm + level*4*IMG_W, 4-row rings indexed by (row & 3).
__device__ __forceinline__ float4 delta_at(const float* __restrict__ sm,
                                           int j, int y, int g) {
    const float NINF = -__int_as_float(0x7f800000);
    const int x4 = 4 * g;
    const float* Lb = sm + (j + 1) * 4 * IMG_W;
    const float* ra = Lb + ((y - 1) & 3) * IMG_W;
    const float* rb = Lb + (y & 3) * IMG_W;
    const float* rc = Lb + ((y + 1) & 3) * IMG_W;
    float4 a = ld4(ra + x4);
    float4 b = ld4(rb + x4);
    float4 c = ld4(rc + x4);
    float al = (g == 0) ? NINF : ra[x4 - 1];
    float bl = (g == 0) ? NINF : rb[x4 - 1];
    float cl = (g == 0) ? NINF : rc[x4 - 1];
    float ar = (g == GROUPS - 1) ? NINF : ra[x4 + 4];
    float br = (g == GROUPS - 1) ? NINF : rb[x4 + 4];
    float cr = (g == GROUPS - 1) ? NINF : rc[x4 + 4];
    if (y == 0)         { a = make_float4(NINF, NINF, NINF, NINF); al = NINF; ar = NINF; }
    if (y == IMG_H - 1) { c = make_float4(NINF, NINF, NINF, NINF); cl = NINF; cr = NINF; }

    float4 vm;
    vm.x = mx3(a.x, b.x, c.x);
    vm.y = mx3(a.y, b.y, c.y);
    vm.z = mx3(a.z, b.z, c.z);
    vm.w = mx3(a.w, b.w, c.w);
    const float vl = mx3(al, bl, cl);
    const float vr = mx3(ar, br, cr);
    float4 op;
    op.x = fmaxf(vm.x, fmaxf(vl,   vm.y));
    op.y = fmaxf(vm.y, fmaxf(vm.x, vm.z));
    op.z = fmaxf(vm.z, fmaxf(vm.y, vm.w));
    op.w = fmaxf(vm.w, fmaxf(vm.z, vr));

    const float* La = sm + j * 4 * IMG_W + (y & 3) * IMG_W;
    const float4 e = ld4(La + x4);
    float4 dl;
    dl.x = fmaxf(e.x - op.x, 0.0f);
    dl.y = fmaxf(e.y - op.y, 0.0f);
    dl.z = fmaxf(e.z - op.z, 0.0f);
    dl.w = fmaxf(e.w - op.w, 0.0f);
    return dl;
}

// Erosion-tower pass, 2-row stepping, 512 threads.
// Levels L_0..L_T (L_j = erode^j(input)); deltas j=0..T-1; skel recurrence in a smem ring.
template <int T, bool INIT, bool WRITE_E>
__global__ __launch_bounds__(NTHR)
void tower_pass(const float* __restrict__ gin,
                float* __restrict__ geout,
                float* __restrict__ gskel)
{
    extern __shared__ float sm[];   // (T+1) level rings (4 rows) + skel ring (SKELD rows)
    const int tid = threadIdx.x;
    const int g   = tid & (GROUPS - 1);
    const int rs  = tid >> 8;       // 0 or 1 : row offset within the 2-row step
    const int y0  = blockIdx.x * BAND;
    const int y1  = y0 + BAND;
    const int n   = blockIdx.y;
    const float INF = __int_as_float(0x7f800000);

    const float4* in4   = (const float4*)(gin + (size_t)n * IMG_PIX);
    float4*       eout4 = (float4*)(WRITE_E ? (geout + (size_t)n * IMG_PIX) : nullptr);
    float4*       skel4 = (float4*)(gskel + (size_t)n * IMG_PIX);

    float* const skelring = sm + (T + 1) * 4 * IMG_W;
    const int x4 = 4 * g;

    // Prefill level rings with +inf
    {
        const float4 inf4 = make_float4(INF, INF, INF, INF);
        float4* s4 = (float4*)sm;
        const int tot = (T + 1) * 4 * GROUPS;
        for (int i = tid; i < tot; i += NTHR) s4[i] = inf4;
    }
    __syncthreads();

    for (int Y = y0 - T - 2; Y <= y1 + T; Y += 2) {
        // Phase 0: load rows Y, Y+1 into level-0 ring (+inf outside image)
        {
            const int row = Y + rs;
            float4 v = make_float4(INF, INF, INF, INF);
            if (row >= 0 && row < IMG_H) v = in4[row * GROUPS + g];
            st4(sm + (row & 3) * IMG_W + x4, v);
        }
        __syncthreads();

        // Phase 1: erosion levels; level j computes rows Y-j, Y+1-j
#pragma unroll
        for (int j = 1; j <= T; ++j) {
            const int r = Y + rs - j;
            float4 o;
            if (r < 0 || r >= IMG_H) {
                o = make_float4(INF, INF, INF, INF);
            } else {
                const float* L  = sm + (j - 1) * 4 * IMG_W;
                const float* ru = L + ((r - 1) & 3) * IMG_W;
                const float* rc = L + (r & 3) * IMG_W;
                const float* rd = L + ((r + 1) & 3) * IMG_W;
                const float4 u = ld4(ru + x4);
                const float4 c = ld4(rc + x4);
                const float4 d = ld4(rd + x4);
                const float cl = (g == 0)          ? INF : rc[x4 - 1];
                const float cr = (g == GROUPS - 1) ? INF : rc[x4 + 4];
                o.x = fminf(mn3(u.x, c.x, d.x), fminf(cl,  c.y));
                o.y = fminf(mn3(u.y, c.y, d.y), fminf(c.x, c.z));
                o.z = fminf(mn3(u.z, c.z, d.z), fminf(c.y, c.w));
                o.w = fminf(mn3(u.w, c.w, d.w), fminf(c.z, cr));
            }
            st4(sm + (j * 4 + (r & 3)) * IMG_W + x4, o);
            if (WRITE_E && j == T) {
                if (r >= y0 && r < y1) eout4[r * GROUPS + g] = o;
            }
            __syncthreads();
        }

        // Phase 2: skel updates. Each item = (i, group); row y = Y-2-i gets
        // updates from levels j0..j1 applied sequentially by ONE thread.
        for (int idx = tid; idx < (T + 1) * GROUPS; idx += NTHR) {
            const int i  = (idx >> 8) - 1;          // -1 .. T-1
            const int gg = idx & (GROUPS - 1);
            const int y  = Y - 2 - i;
            if (y < y0 || y >= y1) continue;

            const int j0 = (i >= 0) ? i : 0;
            const int j1 = (i + 1 < T) ? i + 1 : T - 1;

            float* srow = skelring + (y % SKELD) * IMG_W + 4 * gg;
            float4 s;
            if (j0 == 0) {
                if (INIT) s = make_float4(0.0f, 0.0f, 0.0f, 0.0f);
                else      s = skel4[y * GROUPS + gg];
            } else {
                s = ld4(srow);
            }

            {
                float4 d = delta_at(sm, j0, y, gg);
                skel_upd(s, d);
            }
            if (j1 > j0) {
                float4 d = delta_at(sm, j1, y, gg);
                skel_upd(s, d);
            }

            if (j1 == T - 1) skel4[y * GROUPS + gg] = s;
            else             st4(srow, s);
        }
        __syncthreads();
    }
}

__global__ void zero_sums(double* sums) {
    if (threadIdx.x < 4) sums[threadIdx.x] = 0.0;
}

__global__ __launch_bounds__(256) void reduce_skel(const float* __restrict__ skel,
                                                   const float* __restrict__ other,
                                                   double* __restrict__ sums, int base) {
    const size_t n4 = TOTAL_PIX / 4;
    const float4* s4 = (const float4*)skel;
    const float4* o4 = (const float4*)other;

    float acc_p = 0.0f, acc_s = 0.0f;
    const size_t stride = (size_t)gridDim.x * blockDim.x;
    for (size_t i = (size_t)blockIdx.x * blockDim.x + threadIdx.x; i < n4; i += stride) {
        const float4 a = s4[i];
        const float4 b = o4[i];
        acc_p += a.x * b.x + a.y * b.y + a.z * b.z + a.w * b.w;
        acc_s += a.x + a.y + a.z + a.w;
    }
#pragma unroll
    for (int off = 16; off > 0; off >>= 1) {
        acc_p += __shfl_down_sync(0xffffffffu, acc_p, off);
        acc_s += __shfl_down_sync(0xffffffffu, acc_s, off);
    }
    if ((threadIdx.x & 31) == 0) {
        atomicAdd(&sums[base],     (double)acc_p);
        atomicAdd(&sums[base + 1], (double)acc_s);
    }
}

__global__ void finalize_cldice(const double* __restrict__ sums, float* __restrict__ out) {
    const double tprec = (sums[0] + SMOOTH) / (sums[1] + SMOOTH);
    const double tsens = (sums[2] + SMOOTH) / (sums[3] + SMOOTH);
    out[0] = (float)(1.0 - 2.0 * (tprec * tsens) / (tprec + tsens));
}

extern "C" void kernel_launch(void* const* d_in, const int* in_sizes, int n_in,
                              void* d_out, int out_size) {
    const float* target = (const float*)d_in[0];
    const float* inputs = (const float*)d_in[1];
    float* out = (float*)d_out;

    static float* bufA = nullptr;
    static float* bufB = nullptr;
    static float* skel = nullptr;
    static double* sums = nullptr;
    static bool attr_done = false;
    if (!bufA) {
        cudaGetSymbolAddress((void**)&bufA, g_bufA);
        cudaGetSymbolAddress((void**)&bufB, g_bufB);
        cudaGetSymbolAddress((void**)&skel, g_skel);
        cudaGetSymbolAddress((void**)&sums, g_sums);
    }
    const int SM9 = (10 * 4 + SKELD) * IMG_W * 4;  // 212992 B
    const int SM8 = (9 * 4 + SKELD) * IMG_W * 4;   // 196608 B
    if (!attr_done) {
        cudaFuncSetAttribute(tower_pass<9, true,  true >, cudaFuncAttributeMaxDynamicSharedMemorySize, SM9);
        cudaFuncSetAttribute(tower_pass<9, false, true >, cudaFuncAttributeMaxDynamicSharedMemorySize, SM9);
        cudaFuncSetAttribute(tower_pass<8, false, false>, cudaFuncAttributeMaxDynamicSharedMemorySize, SM8);
        attr_done = true;
    }

    const dim3 grid(NBANDS, N_IMG);
    const dim3 block(NTHR);

    zero_sums<<<1, 32>>>(sums);

    for (int tt = 0; tt < 2; tt++) {
        const float* x     = (tt == 0) ? inputs : target;
        const float* other = (tt == 0) ? target : inputs;

        tower_pass<9, true,  true ><<<grid, block, SM9>>>(x,    bufA,    skel);
        tower_pass<9, false, true ><<<grid, block, SM9>>>(bufA, bufB,    skel);
        tower_pass<8, false, false><<<grid, block, SM8>>>(bufB, nullptr, skel);

        reduce_skel<<<2048, 256>>>(skel, other, sums, tt * 2);
    }

    finalize_cldice<<<1, 1>>>(sums, out);
}